// round 15
// baseline (speedup 1.0000x reference)
#include <cuda_runtime.h>
#include <cuda_fp16.h>
#include <math.h>
#include <stdint.h>

// Problem constants (fixed by the dataset)
#define BB 2
#define NN 50000
#define DD 128
#define EE 500000
#define RR 500
#define ROWS (BB * NN)          // 100000 node-rows

// Scratch (static device globals — no runtime allocation)
__device__ __align__(16) __half   g_p[ROWS * DD];    // (h@msg_W)*sig(h@gate_W) fp16, 25.6MB
__device__ __align__(16) __half   g_rel[RR * DD];    // rel_emb fp16, 128KB (L1-resident)
__device__ __align__(16) __half   g_agg[ROWS * DD];  // fp16 scatter-add target, 25.6MB
__device__ __align__(16) __half   g_Bp_msg[16384];   // permuted msg_W  fp16, 32KB
__device__ __align__(16) __half   g_Bp_gate[16384];  // permuted gate_W fp16, 32KB
__device__ __align__(16) __half   g_Bp_upd[32768];   // permuted update_W fp16, 64KB

// ---------------------------------------------------------------------------
// fp16 mma helper: m16n8k16, fp32 accumulate
// ---------------------------------------------------------------------------
__device__ __forceinline__ void mma_f16(float c[4], const uint32_t a[4],
                                        const uint32_t b[2]) {
    asm volatile(
        "mma.sync.aligned.m16n8k16.row.col.f32.f16.f16.f32 "
        "{%0,%1,%2,%3}, {%4,%5,%6,%7}, {%8,%9}, {%0,%1,%2,%3};"
        : "+f"(c[0]), "+f"(c[1]), "+f"(c[2]), "+f"(c[3])
        : "r"(a[0]), "r"(a[1]), "r"(a[2]), "r"(a[3]), "r"(b[0]), "r"(b[1]));
}

// Shared layout (both GEMM kernels):
//   region0: 16896 fp32 words = X[64][132] for LN epilogue;
//            first 4352 words reused as fp16 A[64][136] during mainloop
//   region1: B fragment-permuted fp16, 8192 words (one 128x128 stage)
#define XWORDS (64 * 132)
#define BWORDS 8192
#define GEMM_SMEM ((XWORDS + BWORDS) * 4)   // 100352 B -> 2 CTAs/SM

// ---------------------------------------------------------------------------
// Setup: permute weights into fp16 m16n8k16 B-fragment order; rel_emb -> fp16.
// ---------------------------------------------------------------------------
__global__ void permute_W_kernel(const float* __restrict__ msg_W,
                                 const float* __restrict__ gate_W,
                                 const float* __restrict__ upd_W,
                                 const float* __restrict__ rel_emb)
{
    const int tid = threadIdx.x;

    if (blockIdx.x >= 16) {   // rel_emb -> fp16, 4 slices
        int slice = blockIdx.x - 16;
        int total = RR * DD / 2;
        int per = (total + 3) / 4;
        int lo = slice * per, hi = min(lo + per, total);
        for (int i = lo + tid; i < hi; i += 256) {
            float2 v = ((const float2*)rel_emb)[i];
            ((__half2*)g_rel)[i] = __floats2half2_rn(v.x, v.y);
        }
        return;
    }

    const int job = blockIdx.x >> 2;        // 0..3: which 128x128 chunk
    const int slice = blockIdx.x & 3;
    const float* src;
    __half* dst;
    if (job == 0)      { src = msg_W;  dst = g_Bp_msg; }
    else if (job == 1) { src = gate_W; dst = g_Bp_gate; }
    else               { src = upd_W + (job - 2) * 128 * 128;
                         dst = g_Bp_upd + (job - 2) * 16384; }

    const float4* W4 = (const float4*)src;
    for (int ii = tid; ii < 32 * 32; ii += 256) {
        int i = slice * 32 * 32 + ii;       // i in [0, 128*32)
        int k = i >> 5, n4 = (i & 31) * 4;
        float4 v = W4[i];
        float vv[4] = {v.x, v.y, v.z, v.w};
        int kt = k >> 4, kk = k & 15;
        int t = (kk & 7) >> 1, slot = kk >> 3, hp = kk & 1;
#pragma unroll
        for (int j = 0; j < 4; j++) {
            int nn = n4 + j;
            int lane = ((nn & 7) << 2) | t;
            int idx = ((((kt << 4) | (nn >> 3)) << 5 | lane) * 2 + slot) * 2 + hp;
            dst[idx] = __float2half_rn(vv[j]);
        }
    }
}

// ---------------------------------------------------------------------------
// Mainloop: warp tile 32x32 over K=128 (8 k-steps of 16), fp16 HMMA.
// ---------------------------------------------------------------------------
__device__ __forceinline__ void mma_mainloop(
    const __half* __restrict__ A0, const uint32_t* __restrict__ Bw,
    float (&acc)[2][4][4])
{
#pragma unroll
    for (int ks = 0; ks < 8; ks++) {
        uint32_t af[2][4];
#pragma unroll
        for (int mt = 0; mt < 2; mt++) {
            const __half* ap = A0 + mt * 2176 + ks * 16;   // 2176 = 16*136
            af[mt][0] = *(const uint32_t*)(ap);             // (r,   klo)
            af[mt][1] = *(const uint32_t*)(ap + 1088);      // (r+8, klo)
            af[mt][2] = *(const uint32_t*)(ap + 8);         // (r,   khi)
            af[mt][3] = *(const uint32_t*)(ap + 1096);      // (r+8, khi)
        }
#pragma unroll
        for (int nt = 0; nt < 4; nt++) {
            uint2 bv = *(const uint2*)(Bw + ks * 1024 + nt * 64);
            uint32_t bf[2] = {bv.x, bv.y};
            mma_f16(acc[0][nt], af[0], bf);
            mma_f16(acc[1][nt], af[1], bf);
        }
    }
}

// Coalesced A-tile fill: fp32 source [ROWS][128] -> fp16 Ash[64][136]
__device__ __forceinline__ void fill_A(__half* Ash, const float4* __restrict__ src4,
                                       int m0, int tid)
{
#pragma unroll
    for (int it = 0; it < 8; it++) {
        int i = tid + it * 256;
        int m = i >> 5, c = i & 31;
        int row = m0 + m;
        float4 v = (row < ROWS) ? src4[row * 32 + c]
                                : make_float4(0.f, 0.f, 0.f, 0.f);
        __half2 h01 = __floats2half2_rn(v.x, v.y);
        __half2 h23 = __floats2half2_rn(v.z, v.w);
        uint2 t;
        t.x = *(uint32_t*)&h01;
        t.y = *(uint32_t*)&h23;
        *(uint2*)&Ash[m * 136 + c * 4] = t;
    }
}

// fp16 source [ROWS][128] -> fp16 Ash[64][136]  (straight layout copy)
__device__ __forceinline__ void fill_A_h16(__half* Ash, const uint2* __restrict__ src2,
                                           int m0, int tid)
{
#pragma unroll
    for (int it = 0; it < 8; it++) {
        int i = tid + it * 256;
        int m = i >> 5, c = i & 31;
        int row = m0 + m;
        uint2 v = (row < ROWS) ? src2[row * 32 + c] : make_uint2(0u, 0u);
        *(uint2*)&Ash[m * 136 + c * 4] = v;
    }
}

// ---------------------------------------------------------------------------
// Kernel 1: p = (h @ msg_W) * sigmoid(h @ gate_W)  -> fp16
// ---------------------------------------------------------------------------
__global__ __launch_bounds__(256, 2) void node_p_mma(const float* __restrict__ h)
{
    extern __shared__ uint32_t sh[];
    __half*   Ash = (__half*)sh;      // [64][136] fp16
    uint32_t* Bs  = sh + XWORDS;      // 8192 words

    const int tid  = threadIdx.x;
    const int m0   = blockIdx.x * 64;
    const int lane = tid & 31, wid = tid >> 5;
    const int wm = wid >> 2, wn = wid & 3;

    fill_A(Ash, (const float4*)h, m0, tid);

    float accM[2][4][4], accG[2][4][4];
#pragma unroll
    for (int mt = 0; mt < 2; mt++)
#pragma unroll
        for (int nt = 0; nt < 4; nt++)
#pragma unroll
            for (int q = 0; q < 4; q++) { accM[mt][nt][q] = 0.f; accG[mt][nt][q] = 0.f; }

    const __half*   A0 = Ash + (wm * 32 + (lane >> 2)) * 136 + (lane & 3) * 2;
    const uint32_t* Bw = Bs + ((wn * 4) << 6) + lane * 2;

    {   // Stage 0: msg_W
        const uint4* src = (const uint4*)g_Bp_msg;
#pragma unroll
        for (int it = 0; it < 8; it++) ((uint4*)Bs)[tid + it * 256] = src[tid + it * 256];
        __syncthreads();
        mma_mainloop(A0, Bw, accM);
    }
    {   // Stage 1: gate_W
        __syncthreads();
        const uint4* src = (const uint4*)g_Bp_gate;
#pragma unroll
        for (int it = 0; it < 8; it++) ((uint4*)Bs)[tid + it * 256] = src[tid + it * 256];
        __syncthreads();
        mma_mainloop(A0, Bw, accG);
    }

    // Epilogue: p = accM * sigmoid(accG) -> fp16 smem stage (stride 68 half2)
    __syncthreads();
    __half2* Psh = (__half2*)sh;            // [64][68 half2]
    {
        const int r = lane >> 2;
        const int colh = (lane & 3);
#pragma unroll
        for (int mt = 0; mt < 2; mt++)
#pragma unroll
            for (int nt = 0; nt < 4; nt++) {
                int rr = wm * 32 + mt * 16 + r;
                int ch = wn * 16 + nt * 4 + colh;
                float s0 = 1.f / (1.f + __expf(-accG[mt][nt][0]));
                float s1 = 1.f / (1.f + __expf(-accG[mt][nt][1]));
                float s2 = 1.f / (1.f + __expf(-accG[mt][nt][2]));
                float s3 = 1.f / (1.f + __expf(-accG[mt][nt][3]));
                Psh[rr * 68 + ch]       = __floats2half2_rn(accM[mt][nt][0] * s0,
                                                            accM[mt][nt][1] * s1);
                Psh[(rr + 8) * 68 + ch] = __floats2half2_rn(accM[mt][nt][2] * s2,
                                                            accM[mt][nt][3] * s3);
            }
    }
    __syncthreads();
#pragma unroll
    for (int it = 0; it < 4; it++) {
        int i = tid + it * 256;
        int m = i >> 4, c = i & 15;
        int row = m0 + m;
        if (row < ROWS)
            ((uint4*)g_p)[row * 16 + c] = *(uint4*)&Psh[m * 68 + c * 4];
    }
}

// ---------------------------------------------------------------------------
// Kernel 2: edge scatter. One warp per edge; both batches.
//   agg16[b, tgt] += fp16( p16[b, src] * rel16[rel] )   via red.add.v2.f16x2
// ---------------------------------------------------------------------------
__global__ __launch_bounds__(256) void edge_scatter_kernel(
    const int* __restrict__ esrc,
    const int* __restrict__ etgt,
    const int* __restrict__ erel)
{
    const int gw   = (blockIdx.x * blockDim.x + threadIdx.x) >> 5;
    const int lane = threadIdx.x & 31;
    if (gw >= EE) return;

    const int s = esrc[gw];
    const int t = etgt[gw];
    const int r = erel[gw];

    const uint2* P2 = (const uint2*)g_p;     // [ROWS][32] uint2 (4 half each)
    const uint2* R2 = (const uint2*)g_rel;   // [RR][32]

    uint2 rl = R2[r * 32 + lane];
    float2 r0 = __half22float2(*(const __half2*)&rl.x);
    float2 r1 = __half22float2(*(const __half2*)&rl.y);

#pragma unroll
    for (int b = 0; b < BB; b++) {
        uint2 pr = P2[(b * NN + s) * 32 + lane];
        float2 p0 = __half22float2(*(const __half2*)&pr.x);
        float2 p1 = __half22float2(*(const __half2*)&pr.y);
        __half2 o01 = __floats2half2_rn(p0.x * r0.x, p0.y * r0.y);
        __half2 o23 = __floats2half2_rn(p1.x * r1.x, p1.y * r1.y);
        __half* q = &g_agg[((b * NN + t) * 32 + lane) * 4];
        asm volatile("red.global.add.noftz.v2.f16x2 [%0], {%1, %2};"
                     :: "l"(q), "r"(*(uint32_t*)&o01), "r"(*(uint32_t*)&o23)
                     : "memory");
    }
}

// ---------------------------------------------------------------------------
// Kernel 3: upd = [h | agg] @ update_W + b ; x = h + relu(upd) ; out = LN(x)
// K=256 in two fp16 stages of 128.
// ---------------------------------------------------------------------------
__global__ __launch_bounds__(256, 2) void update_ln_mma(
    const float* __restrict__ h,
    const float* __restrict__ update_b,
    const float* __restrict__ ln_gamma,
    const float* __restrict__ ln_beta,
    float* __restrict__ out)
{
    extern __shared__ uint32_t sh[];
    __half*   Ash = (__half*)sh;      // [64][136] fp16 (A stage)
    float*    Xsh = (float*)sh;       // [64][132] fp32 (LN stage, same region)
    uint32_t* Bs  = sh + XWORDS;      // 8192 words

    const int tid  = threadIdx.x;
    const int m0   = blockIdx.x * 64;
    const int lane = tid & 31, wid = tid >> 5;
    const int wm = wid >> 2, wn = wid & 3;

    float acc[2][4][4];
#pragma unroll
    for (int mt = 0; mt < 2; mt++)
#pragma unroll
        for (int nt = 0; nt < 4; nt++)
#pragma unroll
            for (int q = 0; q < 4; q++) acc[mt][nt][q] = 0.f;

    const __half*   A0 = Ash + (wm * 32 + (lane >> 2)) * 136 + (lane & 3) * 2;
    const uint32_t* Bw = Bs + ((wn * 4) << 6) + lane * 2;

#pragma unroll
    for (int s = 0; s < 2; s++) {
        if (s) __syncthreads();
        const uint4* bsrc = (const uint4*)g_Bp_upd + s * 2048;
#pragma unroll
        for (int it = 0; it < 8; it++) ((uint4*)Bs)[tid + it * 256] = bsrc[tid + it * 256];
        if (s == 0) fill_A(Ash, (const float4*)h, m0, tid);
        else        fill_A_h16(Ash, (const uint2*)g_agg, m0, tid);
        __syncthreads();
        mma_mainloop(A0, Bw, acc);
    }

    // Epilogue: X = relu(acc + bias) -> Xsh fp32 (residual added in LN pass)
    __syncthreads();
    {
        const int r = lane >> 2, c2 = (lane & 3) * 2;
#pragma unroll
        for (int mt = 0; mt < 2; mt++)
#pragma unroll
            for (int nt = 0; nt < 4; nt++) {
                int rr  = wm * 32 + mt * 16 + r;
                int col = wn * 32 + nt * 8 + c2;
                float b0 = __ldg(&update_b[col]);
                float b1 = __ldg(&update_b[col + 1]);
                float v0 = fmaxf(acc[mt][nt][0] + b0, 0.f);
                float v1 = fmaxf(acc[mt][nt][1] + b1, 0.f);
                float v2 = fmaxf(acc[mt][nt][2] + b0, 0.f);
                float v3 = fmaxf(acc[mt][nt][3] + b1, 0.f);
                *(float2*)&Xsh[rr * 132 + col]       = make_float2(v0, v1);
                *(float2*)&Xsh[(rr + 8) * 132 + col] = make_float2(v2, v3);
            }
    }
    __syncthreads();

    // LayerNorm: 8 warps x 8 rows; residual h added here (coalesced read)
    {
        const float4 gm = ((const float4*)ln_gamma)[lane];
        const float4 bt = ((const float4*)ln_beta)[lane];
        const float4* h4 = (const float4*)h;
        for (int rr = wid; rr < 64; rr += 8) {
            int row = m0 + rr;
            if (row >= ROWS) continue;
            float4 xv = *(const float4*)&Xsh[rr * 132 + lane * 4];
            float4 hv = h4[row * 32 + lane];
            float4 x = make_float4(xv.x + hv.x, xv.y + hv.y,
                                   xv.z + hv.z, xv.w + hv.w);
            float sum = x.x + x.y + x.z + x.w;
            float sq  = x.x * x.x + x.y * x.y + x.z * x.z + x.w * x.w;
#pragma unroll
            for (int off = 16; off; off >>= 1) {
                sum += __shfl_xor_sync(0xffffffffu, sum, off);
                sq  += __shfl_xor_sync(0xffffffffu, sq, off);
            }
            float mu  = sum * (1.f / 128.f);
            float var = sq * (1.f / 128.f) - mu * mu;
            float inv = rsqrtf(var + 1e-5f);
            float4 o;
            o.x = (x.x - mu) * inv * gm.x + bt.x;
            o.y = (x.y - mu) * inv * gm.y + bt.y;
            o.z = (x.z - mu) * inv * gm.z + bt.z;
            o.w = (x.w - mu) * inv * gm.w + bt.w;
            ((float4*)out)[row * 32 + lane] = o;
        }
    }
}

// ---------------------------------------------------------------------------
extern "C" void kernel_launch(void* const* d_in, const int* in_sizes, int n_in,
                              void* d_out, int out_size)
{
    const float* h        = (const float*)d_in[0];
    const int*   esrc     = (const int*)d_in[1];
    const int*   etgt     = (const int*)d_in[2];
    const int*   erel     = (const int*)d_in[3];
    // d_in[4] = nE (== NN, unused)
    const float* msg_W    = (const float*)d_in[5];
    const float* rel_emb  = (const float*)d_in[6];
    const float* gate_W   = (const float*)d_in[7];
    const float* update_W = (const float*)d_in[8];
    const float* update_b = (const float*)d_in[9];
    const float* gamma    = (const float*)d_in[10];
    const float* beta     = (const float*)d_in[11];
    float*       out      = (float*)d_out;

    cudaFuncSetAttribute(node_p_mma,
                         cudaFuncAttributeMaxDynamicSharedMemorySize, GEMM_SMEM);
    cudaFuncSetAttribute(update_ln_mma,
                         cudaFuncAttributeMaxDynamicSharedMemorySize, GEMM_SMEM);

    // Side stream: g_agg memset overlaps permW + node_p.
    cudaStream_t s1;
    cudaStreamCreateWithFlags(&s1, cudaStreamNonBlocking);
    cudaEvent_t eFork, eJoin;
    cudaEventCreateWithFlags(&eFork, cudaEventDisableTiming);
    cudaEventCreateWithFlags(&eJoin, cudaEventDisableTiming);

    cudaEventRecord(eFork, 0);
    cudaStreamWaitEvent(s1, eFork, 0);
    {
        void* agg_ptr = nullptr;
        cudaGetSymbolAddress(&agg_ptr, g_agg);
        cudaMemsetAsync(agg_ptr, 0, sizeof(__half) * ROWS * DD, s1);
    }
    cudaEventRecord(eJoin, s1);

    permute_W_kernel<<<20, 256>>>(msg_W, gate_W, update_W, rel_emb);

    const int mtiles = (ROWS + 63) / 64;    // 1563
    node_p_mma<<<mtiles, 256, GEMM_SMEM>>>(h);

    // edge_scatter needs both node_p (main stream) and the memset (s1)
    cudaStreamWaitEvent(0, eJoin, 0);
    {
        long long total_threads = (long long)EE * 32;
        int blocks = (int)((total_threads + 255) / 256);   // 62500
        edge_scatter_kernel<<<blocks, 256>>>(esrc, etgt, erel);
    }

    update_ln_mma<<<mtiles, 256, GEMM_SMEM>>>(h, update_b, gamma, beta, out);
}

// round 16
// speedup vs baseline: 1.3007x; 1.3007x over previous
#include <cuda_runtime.h>
#include <cuda_fp16.h>
#include <math.h>
#include <stdint.h>

// Problem constants (fixed by the dataset)
#define BB 2
#define NN 50000
#define DD 128
#define EE 500000
#define RR 500
#define ROWS (BB * NN)          // 100000 node-rows

// Scratch (static device globals — no runtime allocation)
__device__ __align__(16) __half   g_p[ROWS * DD];    // (h@msg_W)*sig(h@gate_W) fp16, 25.6MB
__device__ __align__(16) __half   g_rel[RR * DD];    // rel_emb fp16, 128KB (L1-resident)
__device__ __align__(16) float    g_agg[ROWS * DD];  // fp32 scatter-add target, 51.2MB
__device__ __align__(16) __half   g_Bp_msg[16384];   // permuted msg_W  fp16, 32KB
__device__ __align__(16) __half   g_Bp_gate[16384];  // permuted gate_W fp16, 32KB
__device__ __align__(16) __half   g_Bp_upd[32768];   // permuted update_W fp16, 64KB

// ---------------------------------------------------------------------------
// fp16 mma helper: m16n8k16, fp32 accumulate
// ---------------------------------------------------------------------------
__device__ __forceinline__ void mma_f16(float c[4], const uint32_t a[4],
                                        const uint32_t b[2]) {
    asm volatile(
        "mma.sync.aligned.m16n8k16.row.col.f32.f16.f16.f32 "
        "{%0,%1,%2,%3}, {%4,%5,%6,%7}, {%8,%9}, {%0,%1,%2,%3};"
        : "+f"(c[0]), "+f"(c[1]), "+f"(c[2]), "+f"(c[3])
        : "r"(a[0]), "r"(a[1]), "r"(a[2]), "r"(a[3]), "r"(b[0]), "r"(b[1]));
}

// Shared layout (both GEMM kernels):
//   region0: 16896 fp32 words = X[64][132] for LN epilogue;
//            first 4352 words reused as fp16 A[64][136] during mainloop
//   region1: B fragment-permuted fp16, 8192 words (one 128x128 stage)
#define XWORDS (64 * 132)
#define BWORDS 8192
#define GEMM_SMEM ((XWORDS + BWORDS) * 4)   // 100352 B -> 2 CTAs/SM

// ---------------------------------------------------------------------------
// Setup: permute weights into fp16 m16n8k16 B-fragment order; rel_emb -> fp16.
// ---------------------------------------------------------------------------
__global__ void permute_W_kernel(const float* __restrict__ msg_W,
                                 const float* __restrict__ gate_W,
                                 const float* __restrict__ upd_W,
                                 const float* __restrict__ rel_emb)
{
    const int tid = threadIdx.x;

    if (blockIdx.x >= 16) {   // rel_emb -> fp16, 4 slices
        int slice = blockIdx.x - 16;
        int total = RR * DD / 2;
        int per = (total + 3) / 4;
        int lo = slice * per, hi = min(lo + per, total);
        for (int i = lo + tid; i < hi; i += 256) {
            float2 v = ((const float2*)rel_emb)[i];
            ((__half2*)g_rel)[i] = __floats2half2_rn(v.x, v.y);
        }
        return;
    }

    const int job = blockIdx.x >> 2;        // 0..3: which 128x128 chunk
    const int slice = blockIdx.x & 3;
    const float* src;
    __half* dst;
    if (job == 0)      { src = msg_W;  dst = g_Bp_msg; }
    else if (job == 1) { src = gate_W; dst = g_Bp_gate; }
    else               { src = upd_W + (job - 2) * 128 * 128;
                         dst = g_Bp_upd + (job - 2) * 16384; }

    const float4* W4 = (const float4*)src;
    for (int ii = tid; ii < 32 * 32; ii += 256) {
        int i = slice * 32 * 32 + ii;       // i in [0, 128*32)
        int k = i >> 5, n4 = (i & 31) * 4;
        float4 v = W4[i];
        float vv[4] = {v.x, v.y, v.z, v.w};
        int kt = k >> 4, kk = k & 15;
        int t = (kk & 7) >> 1, slot = kk >> 3, hp = kk & 1;
#pragma unroll
        for (int j = 0; j < 4; j++) {
            int nn = n4 + j;
            int lane = ((nn & 7) << 2) | t;
            int idx = ((((kt << 4) | (nn >> 3)) << 5 | lane) * 2 + slot) * 2 + hp;
            dst[idx] = __float2half_rn(vv[j]);
        }
    }
}

// ---------------------------------------------------------------------------
// Mainloop: warp tile 32x32 over K=128 (8 k-steps of 16), fp16 HMMA.
// A frags: ldmatrix.x4 from row-major fp16 Ash (conflict-free).
// B frags: LDS.64 from permuted Bs.
// aAddr0/aAddr1: per-lane smem byte addresses of this lane's fragment row for
// mt=0/1 at ks=0 (lane g=lane>>3 selects tile {(m0,k0),(m8,k0),(m0,k8),(m8,k8)}).
// ---------------------------------------------------------------------------
__device__ __forceinline__ void mma_mainloop(
    uint32_t aAddr0, uint32_t aAddr1, const uint32_t* __restrict__ Bw,
    float (&acc)[2][4][4])
{
#pragma unroll
    for (int ks = 0; ks < 8; ks++) {
        uint32_t af[2][4];
        asm volatile(
            "ldmatrix.sync.aligned.m8n8.x4.shared.b16 {%0,%1,%2,%3}, [%4];"
            : "=r"(af[0][0]), "=r"(af[0][1]), "=r"(af[0][2]), "=r"(af[0][3])
            : "r"(aAddr0 + ks * 32));
        asm volatile(
            "ldmatrix.sync.aligned.m8n8.x4.shared.b16 {%0,%1,%2,%3}, [%4];"
            : "=r"(af[1][0]), "=r"(af[1][1]), "=r"(af[1][2]), "=r"(af[1][3])
            : "r"(aAddr1 + ks * 32));
#pragma unroll
        for (int nt = 0; nt < 4; nt++) {
            uint2 bv = *(const uint2*)(Bw + ks * 1024 + nt * 64);
            uint32_t bf[2] = {bv.x, bv.y};
            mma_f16(acc[0][nt], af[0], bf);
            mma_f16(acc[1][nt], af[1], bf);
        }
    }
}

// Per-lane ldmatrix base address (bytes, smem space) for this warp's A tile.
__device__ __forceinline__ uint32_t ldsm_base(const __half* Ash, int wm, int lane)
{
    int g = lane >> 3, r = lane & 7;
    int m_row  = wm * 32 + (g & 1) * 8 + r;
    int k_half = (g >> 1) * 8;
    return (uint32_t)__cvta_generic_to_shared(Ash) + (m_row * 136 + k_half) * 2;
}

// Coalesced A-tile fill: fp32 source [ROWS][128] -> fp16 Ash[64][136]
__device__ __forceinline__ void fill_A(__half* Ash, const float4* __restrict__ src4,
                                       int m0, int tid)
{
#pragma unroll
    for (int it = 0; it < 8; it++) {
        int i = tid + it * 256;
        int m = i >> 5, c = i & 31;
        int row = m0 + m;
        float4 v = (row < ROWS) ? src4[row * 32 + c]
                                : make_float4(0.f, 0.f, 0.f, 0.f);
        __half2 h01 = __floats2half2_rn(v.x, v.y);
        __half2 h23 = __floats2half2_rn(v.z, v.w);
        uint2 t;
        t.x = *(uint32_t*)&h01;
        t.y = *(uint32_t*)&h23;
        *(uint2*)&Ash[m * 136 + c * 4] = t;
    }
}

// ---------------------------------------------------------------------------
// Kernel 1: p = (h @ msg_W) * sigmoid(h @ gate_W)  -> fp16
// ---------------------------------------------------------------------------
__global__ __launch_bounds__(256, 2) void node_p_mma(const float* __restrict__ h)
{
    extern __shared__ uint32_t sh[];
    __half*   Ash = (__half*)sh;      // [64][136] fp16
    uint32_t* Bs  = sh + XWORDS;      // 8192 words

    const int tid  = threadIdx.x;
    const int m0   = blockIdx.x * 64;
    const int lane = tid & 31, wid = tid >> 5;
    const int wm = wid >> 2, wn = wid & 3;

    fill_A(Ash, (const float4*)h, m0, tid);

    float accM[2][4][4], accG[2][4][4];
#pragma unroll
    for (int mt = 0; mt < 2; mt++)
#pragma unroll
        for (int nt = 0; nt < 4; nt++)
#pragma unroll
            for (int q = 0; q < 4; q++) { accM[mt][nt][q] = 0.f; accG[mt][nt][q] = 0.f; }

    const uint32_t aAddr0 = ldsm_base(Ash, wm, lane);
    const uint32_t aAddr1 = aAddr0 + 16 * 136 * 2;
    const uint32_t* Bw = Bs + ((wn * 4) << 6) + lane * 2;

    {   // Stage 0: msg_W
        const uint4* src = (const uint4*)g_Bp_msg;
#pragma unroll
        for (int it = 0; it < 8; it++) ((uint4*)Bs)[tid + it * 256] = src[tid + it * 256];
        __syncthreads();
        mma_mainloop(aAddr0, aAddr1, Bw, accM);
    }
    {   // Stage 1: gate_W
        __syncthreads();
        const uint4* src = (const uint4*)g_Bp_gate;
#pragma unroll
        for (int it = 0; it < 8; it++) ((uint4*)Bs)[tid + it * 256] = src[tid + it * 256];
        __syncthreads();
        mma_mainloop(aAddr0, aAddr1, Bw, accG);
    }

    // Epilogue: p = accM * sigmoid(accG) -> fp16 smem stage (stride 68 half2)
    __syncthreads();
    __half2* Psh = (__half2*)sh;            // [64][68 half2]
    {
        const int r = lane >> 2;
        const int colh = (lane & 3);
#pragma unroll
        for (int mt = 0; mt < 2; mt++)
#pragma unroll
            for (int nt = 0; nt < 4; nt++) {
                int rr = wm * 32 + mt * 16 + r;
                int ch = wn * 16 + nt * 4 + colh;
                float s0 = 1.f / (1.f + __expf(-accG[mt][nt][0]));
                float s1 = 1.f / (1.f + __expf(-accG[mt][nt][1]));
                float s2 = 1.f / (1.f + __expf(-accG[mt][nt][2]));
                float s3 = 1.f / (1.f + __expf(-accG[mt][nt][3]));
                Psh[rr * 68 + ch]       = __floats2half2_rn(accM[mt][nt][0] * s0,
                                                            accM[mt][nt][1] * s1);
                Psh[(rr + 8) * 68 + ch] = __floats2half2_rn(accM[mt][nt][2] * s2,
                                                            accM[mt][nt][3] * s3);
            }
    }
    __syncthreads();
#pragma unroll
    for (int it = 0; it < 4; it++) {
        int i = tid + it * 256;
        int m = i >> 4, c = i & 15;
        int row = m0 + m;
        if (row < ROWS)
            ((uint4*)g_p)[row * 16 + c] = *(uint4*)&Psh[m * 68 + c * 4];
    }
}

// ---------------------------------------------------------------------------
// Kernel 2: edge scatter. One warp per edge; both batches.
//   agg[b, tgt] += fp32( p16[b, src] * rel16[rel] )   via red.add.v4.f32
// ---------------------------------------------------------------------------
__global__ __launch_bounds__(256) void edge_scatter_kernel(
    const int* __restrict__ esrc,
    const int* __restrict__ etgt,
    const int* __restrict__ erel)
{
    const int gw   = (blockIdx.x * blockDim.x + threadIdx.x) >> 5;
    const int lane = threadIdx.x & 31;
    if (gw >= EE) return;

    const int s = esrc[gw];
    const int t = etgt[gw];
    const int r = erel[gw];

    const uint2* P2 = (const uint2*)g_p;     // [ROWS][32] uint2 (4 half each)
    const uint2* R2 = (const uint2*)g_rel;   // [RR][32]

    uint2 rl = R2[r * 32 + lane];
    float2 r0 = __half22float2(*(const __half2*)&rl.x);
    float2 r1 = __half22float2(*(const __half2*)&rl.y);

#pragma unroll
    for (int b = 0; b < BB; b++) {
        uint2 pr = P2[(b * NN + s) * 32 + lane];
        float2 p0 = __half22float2(*(const __half2*)&pr.x);
        float2 p1 = __half22float2(*(const __half2*)&pr.y);
        float o0 = p0.x * r0.x, o1 = p0.y * r0.y;
        float o2 = p1.x * r1.x, o3 = p1.y * r1.y;
        float* q = &g_agg[((b * NN + t) * 32 + lane) * 4];
        asm volatile("red.global.add.v4.f32 [%0], {%1, %2, %3, %4};"
                     :: "l"(q), "f"(o0), "f"(o1), "f"(o2), "f"(o3)
                     : "memory");
    }
}

// ---------------------------------------------------------------------------
// Kernel 3: upd = [h | agg] @ update_W + b ; x = h + relu(upd) ; out = LN(x)
// K=256 in two fp16 stages of 128.
// ---------------------------------------------------------------------------
__global__ __launch_bounds__(256, 2) void update_ln_mma(
    const float* __restrict__ h,
    const float* __restrict__ update_b,
    const float* __restrict__ ln_gamma,
    const float* __restrict__ ln_beta,
    float* __restrict__ out)
{
    extern __shared__ uint32_t sh[];
    __half*   Ash = (__half*)sh;      // [64][136] fp16 (A stage)
    float*    Xsh = (float*)sh;       // [64][132] fp32 (LN stage, same region)
    uint32_t* Bs  = sh + XWORDS;      // 8192 words

    const int tid  = threadIdx.x;
    const int m0   = blockIdx.x * 64;
    const int lane = tid & 31, wid = tid >> 5;
    const int wm = wid >> 2, wn = wid & 3;

    float acc[2][4][4];
#pragma unroll
    for (int mt = 0; mt < 2; mt++)
#pragma unroll
        for (int nt = 0; nt < 4; nt++)
#pragma unroll
            for (int q = 0; q < 4; q++) acc[mt][nt][q] = 0.f;

    const uint32_t aAddr0 = ldsm_base(Ash, wm, lane);
    const uint32_t aAddr1 = aAddr0 + 16 * 136 * 2;
    const uint32_t* Bw = Bs + ((wn * 4) << 6) + lane * 2;

#pragma unroll
    for (int s = 0; s < 2; s++) {
        if (s) __syncthreads();
        const uint4* bsrc = (const uint4*)g_Bp_upd + s * 2048;
#pragma unroll
        for (int it = 0; it < 8; it++) ((uint4*)Bs)[tid + it * 256] = bsrc[tid + it * 256];
        fill_A(Ash, (const float4*)(s ? g_agg : h), m0, tid);
        __syncthreads();
        mma_mainloop(aAddr0, aAddr1, Bw, acc);
    }

    // Epilogue: X = relu(acc + bias) -> Xsh fp32 (residual added in LN pass)
    __syncthreads();
    {
        const int r = lane >> 2, c2 = (lane & 3) * 2;
#pragma unroll
        for (int mt = 0; mt < 2; mt++)
#pragma unroll
            for (int nt = 0; nt < 4; nt++) {
                int rr  = wm * 32 + mt * 16 + r;
                int col = wn * 32 + nt * 8 + c2;
                float b0 = __ldg(&update_b[col]);
                float b1 = __ldg(&update_b[col + 1]);
                float v0 = fmaxf(acc[mt][nt][0] + b0, 0.f);
                float v1 = fmaxf(acc[mt][nt][1] + b1, 0.f);
                float v2 = fmaxf(acc[mt][nt][2] + b0, 0.f);
                float v3 = fmaxf(acc[mt][nt][3] + b1, 0.f);
                *(float2*)&Xsh[rr * 132 + col]       = make_float2(v0, v1);
                *(float2*)&Xsh[(rr + 8) * 132 + col] = make_float2(v2, v3);
            }
    }
    __syncthreads();

    // LayerNorm: 8 warps x 8 rows; residual h added here (coalesced read)
    {
        const float4 gm = ((const float4*)ln_gamma)[lane];
        const float4 bt = ((const float4*)ln_beta)[lane];
        const float4* h4 = (const float4*)h;
        for (int rr = wid; rr < 64; rr += 8) {
            int row = m0 + rr;
            if (row >= ROWS) continue;
            float4 xv = *(const float4*)&Xsh[rr * 132 + lane * 4];
            float4 hv = h4[row * 32 + lane];
            float4 x = make_float4(xv.x + hv.x, xv.y + hv.y,
                                   xv.z + hv.z, xv.w + hv.w);
            float sum = x.x + x.y + x.z + x.w;
            float sq  = x.x * x.x + x.y * x.y + x.z * x.z + x.w * x.w;
#pragma unroll
            for (int off = 16; off; off >>= 1) {
                sum += __shfl_xor_sync(0xffffffffu, sum, off);
                sq  += __shfl_xor_sync(0xffffffffu, sq, off);
            }
            float mu  = sum * (1.f / 128.f);
            float var = sq * (1.f / 128.f) - mu * mu;
            float inv = rsqrtf(var + 1e-5f);
            float4 o;
            o.x = (x.x - mu) * inv * gm.x + bt.x;
            o.y = (x.y - mu) * inv * gm.y + bt.y;
            o.z = (x.z - mu) * inv * gm.z + bt.z;
            o.w = (x.w - mu) * inv * gm.w + bt.w;
            ((float4*)out)[row * 32 + lane] = o;
        }
    }
}

// ---------------------------------------------------------------------------
extern "C" void kernel_launch(void* const* d_in, const int* in_sizes, int n_in,
                              void* d_out, int out_size)
{
    const float* h        = (const float*)d_in[0];
    const int*   esrc     = (const int*)d_in[1];
    const int*   etgt     = (const int*)d_in[2];
    const int*   erel     = (const int*)d_in[3];
    // d_in[4] = nE (== NN, unused)
    const float* msg_W    = (const float*)d_in[5];
    const float* rel_emb  = (const float*)d_in[6];
    const float* gate_W   = (const float*)d_in[7];
    const float* update_W = (const float*)d_in[8];
    const float* update_b = (const float*)d_in[9];
    const float* gamma    = (const float*)d_in[10];
    const float* beta     = (const float*)d_in[11];
    float*       out      = (float*)d_out;

    cudaFuncSetAttribute(node_p_mma,
                         cudaFuncAttributeMaxDynamicSharedMemorySize, GEMM_SMEM);
    cudaFuncSetAttribute(update_ln_mma,
                         cudaFuncAttributeMaxDynamicSharedMemorySize, GEMM_SMEM);

    // Side stream: g_agg memset overlaps permW + node_p.
    cudaStream_t s1;
    cudaStreamCreateWithFlags(&s1, cudaStreamNonBlocking);
    cudaEvent_t eFork, eJoin;
    cudaEventCreateWithFlags(&eFork, cudaEventDisableTiming);
    cudaEventCreateWithFlags(&eJoin, cudaEventDisableTiming);

    cudaEventRecord(eFork, 0);
    cudaStreamWaitEvent(s1, eFork, 0);
    {
        void* agg_ptr = nullptr;
        cudaGetSymbolAddress(&agg_ptr, g_agg);
        cudaMemsetAsync(agg_ptr, 0, sizeof(float) * ROWS * DD, s1);
    }
    cudaEventRecord(eJoin, s1);

    permute_W_kernel<<<20, 256>>>(msg_W, gate_W, update_W, rel_emb);

    const int mtiles = (ROWS + 63) / 64;    // 1563
    node_p_mma<<<mtiles, 256, GEMM_SMEM>>>(h);

    // edge_scatter needs both node_p (main stream) and the memset (s1)
    cudaStreamWaitEvent(0, eJoin, 0);
    {
        long long total_threads = (long long)EE * 32;
        int blocks = (int)((total_threads + 255) / 256);   // 62500
        edge_scatter_kernel<<<blocks, 256>>>(esrc, etgt, erel);
    }

    update_ln_mma<<<mtiles, 256, GEMM_SMEM>>>(h, update_b, gamma, beta, out);
}